// round 2
// baseline (speedup 1.0000x reference)
#include <cuda_runtime.h>
#include <cuda_bf16.h>

// Retrace: per-(b,d) reverse affine scan + MSE reduction.
// Shapes: B=2048, T=512, D=16. All inputs fp32. Output: 1 fp32 scalar.
// d_in[0]=Q, [1]=expected_target_Q, [2]=target_Q, [3]=rewards,
// [4]=target_policy_probs, [5]=behaviour_policy_probs ([B,T])

#define RB 2048
#define RT 512
#define RD 16
#define GAMMA 0.99f

__global__ __launch_bounds__(256, 4)
void retrace_kernel(const float* __restrict__ Q,
                    const float* __restrict__ eQ,
                    const float* __restrict__ tQ,
                    const float* __restrict__ rw,
                    const float* __restrict__ tpp,
                    const float* __restrict__ bpp,
                    float* __restrict__ out)
{
    const int idx = blockIdx.x * blockDim.x + threadIdx.x;   // 0 .. B*D-1
    const int b = idx >> 4;           // D = 16
    const int d = idx & 15;

    const size_t base = (size_t)b * (RT * RD) + d;
    const float* q_p   = Q   + base;
    const float* e_p   = eQ  + base;
    const float* tq_p  = tQ  + base;
    const float* r_p   = rw  + base;
    const float* tpp_p = tpp + base;
    const float* bpp_p = bpp + (size_t)b * RT;

    float carry = tq_p[(RT - 1) * RD];
    float acc = 0.0f;

    #pragma unroll 4
    for (int t = RT - 2; t >= 0; --t) {
        const int j = t + 1;
        // importance weight c = exp(min(log_pi - log_b, 0))
        float lw = tpp_p[j * RD] - bpp_p[j];
        float c  = __expf(fminf(lw, 0.0f));
        // base term is carry-independent -> off the critical path
        float gc   = GAMMA * c;
        float bse  = fmaf(GAMMA, e_p[j * RD], r_p[t * RD]);
        bse        = fmaf(-gc, tq_p[j * RD], bse);
        float q    = fmaf(gc, carry, bse);       // single fma on carry chain
        float diff = q_p[t * RD] - q;
        acc  = fmaf(diff, diff, acc);
        carry = q;
    }

    // scale by 1 / (B * (T-1) * D)
    const float inv_n = 1.0f / (float)((size_t)RB * (RT - 1) * RD);
    acc *= inv_n;

    // warp reduction
    #pragma unroll
    for (int off = 16; off > 0; off >>= 1)
        acc += __shfl_down_sync(0xFFFFFFFFu, acc, off);

    // block reduction
    __shared__ float warp_sums[8];
    const int lane = threadIdx.x & 31;
    const int wid  = threadIdx.x >> 5;
    if (lane == 0) warp_sums[wid] = acc;
    __syncthreads();
    if (wid == 0) {
        float v = (lane < (blockDim.x >> 5)) ? warp_sums[lane] : 0.0f;
        #pragma unroll
        for (int off = 4; off > 0; off >>= 1)
            v += __shfl_down_sync(0xFFFFFFFFu, v, off);
        if (lane == 0)
            atomicAdd(out, v);
    }
}

extern "C" void kernel_launch(void* const* d_in, const int* in_sizes, int n_in,
                              void* d_out, int out_size)
{
    const float* Q   = (const float*)d_in[0];
    const float* eQ  = (const float*)d_in[1];
    const float* tQ  = (const float*)d_in[2];
    const float* rw  = (const float*)d_in[3];
    const float* tpp = (const float*)d_in[4];
    const float* bpp = (const float*)d_in[5];
    float* out = (float*)d_out;

    cudaMemsetAsync(out, 0, sizeof(float), 0);

    const int total = RB * RD;          // 32768 chains
    const int threads = 256;
    const int blocks = total / threads; // 128
    retrace_kernel<<<blocks, threads>>>(Q, eQ, tQ, rw, tpp, bpp, out);
}

// round 3
// speedup vs baseline: 1.6973x; 1.6973x over previous
#include <cuda_runtime.h>
#include <cuda_bf16.h>

// Retrace: per-(b,d) reverse affine scan + MSE reduction.
// Shapes: B=2048, T=512, D=16. All inputs fp32. Output: 1 fp32 scalar.
// Segment-parallel: q_t = gc_t * q_{t+1} + base_t is affine in the carry, so
// each 64-step segment reduces to (P, S) with q = P*x + S, and its squared-error
// contribution is quadratic in x: sumD2 - 2x*sumDP + x^2*sumP2.
// Block = 32 chains x 8 segments (warp = segment, lane = chain); segments are
// combined serially per chain in shared memory. One global pass, no scratch.

#define RB 2048
#define RT 512
#define RD 16
#define NSEG 8
#define SEGLEN 64        // steps per segment (last segment has 63: t=448..510)
#define CHAINS_PER_BLK 32
#define GAMMA 0.99f

__global__ __launch_bounds__(256, 3)
void retrace_seg_kernel(const float* __restrict__ Q,
                        const float* __restrict__ eQ,
                        const float* __restrict__ tQ,
                        const float* __restrict__ rw,
                        const float* __restrict__ tpp,
                        const float* __restrict__ bpp,
                        float* __restrict__ out)
{
    const int lane = threadIdx.x & 31;       // chain within block
    const int seg  = threadIdx.x >> 5;       // time segment 0..7
    const int chain = blockIdx.x * CHAINS_PER_BLK + lane;  // 0 .. B*D-1
    const int b = chain >> 4;                // D = 16
    const int d = chain & 15;

    const size_t base = (size_t)b * (RT * RD) + d;
    const float* q_p   = Q   + base;
    const float* e_p   = eQ  + base;
    const float* tq_p  = tQ  + base;
    const float* r_p   = rw  + base;
    const float* tpp_p = tpp + base;
    const float* bpp_p = bpp + (size_t)b * RT;

    const int lo = seg * SEGLEN;
    const int hi = (seg == NSEG - 1) ? (RT - 2) : (lo + SEGLEN - 1);

    // Backward scan within segment: q = P*x + S (x = carry entering at t=hi+1)
    float P = 1.0f, S = 0.0f;
    float sumD2 = 0.0f, sumDP = 0.0f, sumP2 = 0.0f;

    #pragma unroll 4
    for (int t = hi; t >= lo; --t) {
        const int j = t + 1;
        float lw  = tpp_p[j * RD] - bpp_p[j];
        float gc  = GAMMA * __expf(fminf(lw, 0.0f));
        float bse = fmaf(GAMMA, e_p[j * RD], r_p[t * RD]);
        bse       = fmaf(-gc, tq_p[j * RD], bse);
        P = gc * P;
        S = fmaf(gc, S, bse);
        float dv = q_p[t * RD] - S;          // diff = dv - P*x
        sumD2 = fmaf(dv, dv, sumD2);
        sumDP = fmaf(dv, P,  sumDP);
        sumP2 = fmaf(P,  P,  sumP2);
    }

    __shared__ float shA [NSEG][CHAINS_PER_BLK];
    __shared__ float shB [NSEG][CHAINS_PER_BLK];
    __shared__ float shD2[NSEG][CHAINS_PER_BLK];
    __shared__ float shDP[NSEG][CHAINS_PER_BLK];
    __shared__ float shP2[NSEG][CHAINS_PER_BLK];
    shA [seg][lane] = P;
    shB [seg][lane] = S;
    shD2[seg][lane] = sumD2;
    shDP[seg][lane] = sumDP;
    shP2[seg][lane] = sumP2;
    __syncthreads();

    // Warp 0: serial combine over 8 segments for each of the 32 chains.
    if (seg == 0) {
        float x = tq_p[(RT - 1) * RD];       // initial carry = target_Q[:, -1]
        float acc = 0.0f;
        #pragma unroll
        for (int s = NSEG - 1; s >= 0; --s) {
            float a2 = shD2[s][lane], dp = shDP[s][lane], p2 = shP2[s][lane];
            acc += fmaf(x, fmaf(x, p2, -2.0f * dp), a2);
            x = fmaf(shA[s][lane], x, shB[s][lane]);
        }
        const float inv_n = 1.0f / (float)((size_t)RB * (RT - 1) * RD);
        acc *= inv_n;

        #pragma unroll
        for (int off = 16; off > 0; off >>= 1)
            acc += __shfl_down_sync(0xFFFFFFFFu, acc, off);
        if (lane == 0)
            atomicAdd(out, acc);
    }
}

extern "C" void kernel_launch(void* const* d_in, const int* in_sizes, int n_in,
                              void* d_out, int out_size)
{
    const float* Q   = (const float*)d_in[0];
    const float* eQ  = (const float*)d_in[1];
    const float* tQ  = (const float*)d_in[2];
    const float* rw  = (const float*)d_in[3];
    const float* tpp = (const float*)d_in[4];
    const float* bpp = (const float*)d_in[5];
    float* out = (float*)d_out;

    cudaMemsetAsync(out, 0, sizeof(float), 0);

    const int blocks = (RB * RD) / CHAINS_PER_BLK;   // 1024
    retrace_seg_kernel<<<blocks, NSEG * 32>>>(Q, eQ, tQ, rw, tpp, bpp, out);
}